// round 10
// baseline (speedup 1.0000x reference)
#include <cuda_runtime.h>
#include <cstdint>

// Problem constants (fixed by the dataset)
#define LL 256

#define WARPS_PER_BLOCK 4
#define THREADS_PER_BLOCK (WARPS_PER_BLOCK * 32)   // 1 warp = 1 batch element
typedef unsigned long long ull;

// ---------- f32x2 packed helpers (Blackwell packed fp32 pipe) ----------
__device__ __forceinline__ ull pack2(float a, float b) {
    ull r;
    asm("mov.b64 %0, {%1, %2};" : "=l"(r)
        : "r"(__float_as_uint(a)), "r"(__float_as_uint(b)));
    return r;
}
__device__ __forceinline__ void unpack2(ull v, float& a, float& b) {
    unsigned int x, y;
    asm("mov.b64 {%0, %1}, %2;" : "=r"(x), "=r"(y) : "l"(v));
    a = __uint_as_float(x);
    b = __uint_as_float(y);
}
__device__ __forceinline__ ull fma2(ull a, ull b, ull c) {
    ull d;
    asm("fma.rn.f32x2 %0, %1, %2, %3;" : "=l"(d) : "l"(a), "l"(b), "l"(c));
    return d;
}
__device__ __forceinline__ ull add2(ull a, ull b) {
    ull d;
    asm("add.rn.f32x2 %0, %1, %2;" : "=l"(d) : "l"(a), "l"(b));
    return d;
}

// HW tanh (MUFU.TANH): ~1e-4 abs error, 1 MUFU op
__device__ __forceinline__ float tanh_fast(float x) {
    float y;
    asm("tanh.approx.f32 %0, %1;" : "=f"(y) : "f"(x));
    return y;
}

// Deferred output head: butterfly-reduce staged (h*wo0, h*wo1), elu +
// 2-class gathered log-softmax. wmask=0 drops the priming pend.
__device__ __forceinline__ float head_update(ull pp, int cur,
                                             float bo0, float bo1,
                                             float wmask, float logp) {
#pragma unroll
    for (int d = 16; d > 0; d >>= 1) {
        ull q = __shfl_xor_sync(0xffffffffu, pp, d);
        pp = add2(pp, q);
    }
    float p0, p1;
    unpack2(pp, p0, p1);
    p0 += bo0;
    p1 += bo1;
    float e0 = (p0 > 0.f) ? p0 : (__expf(p0) - 1.f);
    float e1 = (p1 > 0.f) ? p1 : (__expf(p1) - 1.f);
    float d = cur ? (e0 - e1) : (e1 - e0);   // e_other - e_sel
    return fmaf(wmask, -__logf(1.f + __expf(d)), logp);
}

// Layout: warp = one batch element (measured optimum, R6). Lane j owns
// hidden unit j. Wh column weights for unit j live in registers as f32x2
// pairs (0.5-prescaled on i,f,o so sigmoid(g)=fma(0.5,tanh(g'),0.5)).
// h-broadcast: lane j stores (h_j,h_j) once (STS.64); all lanes read the
// table via broadcast LDS.128 (same-address, conflict-free, halves are
// ready-made f32x2 operands). Output head is software-pipelined one step
// behind so its SHFL/MUFU latency overlaps the FMA loop.
// NEW vs R6: __launch_bounds__(128,4) caps regs at 128 -> 4 blocks/SM ->
// 16 warps/SM (latency cover) and 2 launch waves instead of 3 (grid 1024,
// 592 concurrent). ptxas spills the overflow (~cold state) to local.
__global__ void __launch_bounds__(THREADS_PER_BLOCK, 4)
lstm_kernel(const int* __restrict__ x,       // [B, L] spins in {0,1}
            const float* __restrict__ Wi,    // [2, 128]
            const float* __restrict__ Wh,    // [32, 128]
            const float* __restrict__ bh,    // [128]
            const float* __restrict__ Wo,    // [32, 2]
            const float* __restrict__ bo,    // [2]
            float* __restrict__ out)         // [B]
{
    __shared__ ulonglong2 s_init[3 * 32];  // [sel][lane]: prescaled (Wi[sel]+bh)
    __shared__ ull s_h[WARPS_PER_BLOCK][2][32];  // (h,h) pairs, dbl-buf
    __shared__ unsigned char s_x[WARPS_PER_BLOCK * LL];

    const int tid = threadIdx.x;
    const int lane = tid & 31;
    const int warp = tid >> 5;
    const int b_glob = blockIdx.x * WARPS_PER_BLOCK + warp;
    const int j = lane;

    // ---- setup: init-row table (prescaled: 0.5 on i,f,o; 1.0 on g) ----
    if (tid < 96) {
        int s = tid >> 5;        // 0,1 = spin rows, 2 = bh-only (t=0)
        int jj = tid & 31;
        float ai = bh[jj], af = bh[32 + jj], ag = bh[64 + jj], ao = bh[96 + jj];
        if (s < 2) {
            ai += Wi[s * 128 + jj];
            af += Wi[s * 128 + 32 + jj];
            ag += Wi[s * 128 + 64 + jj];
            ao += Wi[s * 128 + 96 + jj];
        }
        ulonglong2 v;
        v.x = pack2(0.5f * ai, 0.5f * af);
        v.y = pack2(ag, 0.5f * ao);
        s_init[s * 32 + jj] = v;
    }
    {
        const int base = blockIdx.x * WARPS_PER_BLOCK * LL;
        for (int idx = tid; idx < WARPS_PER_BLOCK * LL; idx += THREADS_PER_BLOCK)
            s_x[idx] = (unsigned char)x[base + idx];
    }
    __syncthreads();

    const unsigned char* xb = s_x + warp * LL;

    // ---- register-resident recurrent weights (prescaled) ----
    ull wif[32], wgo[32];
#pragma unroll
    for (int k = 0; k < 32; k++) {
        const float* r = Wh + k * 128;
        wif[k] = pack2(0.5f * r[j], 0.5f * r[32 + j]);
        wgo[k] = pack2(r[64 + j], 0.5f * r[96 + j]);
    }
    const ull wo01 = pack2(Wo[2 * j], Wo[2 * j + 1]);
    const float bo0 = bo[0];
    const float bo1 = bo[1];

    float h = 0.f, c = 0.f, logp = 0.f;
    float wmask = 0.f;                       // masks the priming pend
    ull pend = 0ull;                         // staged (h*wo0, h*wo1)
    int cur_pend = 0;                        // spin of the staged step

    // t=0 gate init: bh-only row (row 2)
    ulonglong2 v0 = s_init[2 * 32 + lane];
    ull selif = v0.x;
    ull selgo = v0.y;

    const ulonglong2* hb0 = reinterpret_cast<const ulonglong2*>(s_h[warp][0]);
    const ulonglong2* hb1 = reinterpret_cast<const ulonglong2*>(s_h[warp][1]);

#pragma unroll 1
    for (int t = 0; t < LL; t += 2) {
#pragma unroll
        for (int half = 0; half < 2; half++) {
            // publish my (h, h) pair to this step's buffer
            s_h[warp][half][lane] = pack2(h, h);
            __syncwarp();
            const ulonglong2* hb = half ? hb1 : hb0;

            // ---- deferred output head of the PREVIOUS step ----
            logp = head_update(pend, cur_pend, bo0, bo1, wmask, logp);

            // ---- gate fma loop: 4 independent accumulator chains ----
            ull aif_a = selif, aif_b = 0ull;
            ull ago_a = selgo, ago_b = 0ull;
#pragma unroll
            for (int k = 0; k < 32; k += 2) {
                ulonglong2 hh = hb[k >> 1];   // broadcast LDS.128
                aif_a = fma2(hh.x, wif[k], aif_a);
                ago_a = fma2(hh.x, wgo[k], ago_a);
                aif_b = fma2(hh.y, wif[k + 1], aif_b);
                ago_b = fma2(hh.y, wgo[k + 1], ago_b);
            }
            ull aif = add2(aif_a, aif_b);
            ull ago = add2(ago_a, ago_b);

            float gi, gf, gg, go;
            unpack2(aif, gi, gf);
            unpack2(ago, gg, go);
            float si = fmaf(0.5f, tanh_fast(gi), 0.5f);   // prescaled sigmoid
            float sf = fmaf(0.5f, tanh_fast(gf), 0.5f);
            float so = fmaf(0.5f, tanh_fast(go), 0.5f);
            float tg = tanh_fast(gg);
            c = fmaf(sf, c, si * tg);
            h = so * tanh_fast(c);

            // ---- stage this step's output head for the next iteration ----
            pend = fma2(pack2(h, h), wo01, 0ull);
            int cur = (int)xb[t + half];
            cur_pend = cur;
            wmask = 1.f;

            // next step's gate-init row (selected by this step's spin)
            ulonglong2 vn = s_init[cur * 32 + lane];
            selif = vn.x;
            selgo = vn.y;
        }
    }

    // flush the last step's pend
    logp = head_update(pend, cur_pend, bo0, bo1, wmask, logp);

    if (lane == 0) {
        out[b_glob] = 0.5f * logp;
    }
}

extern "C" void kernel_launch(void* const* d_in, const int* in_sizes, int n_in,
                              void* d_out, int out_size) {
    const int* x = (const int*)d_in[0];
    const float* Wi = (const float*)d_in[1];
    const float* Wh = (const float*)d_in[2];
    const float* bh = (const float*)d_in[3];
    const float* Wo = (const float*)d_in[4];
    const float* bo = (const float*)d_in[5];
    float* out = (float*)d_out;

    const int batch = in_sizes[0] / LL;              // 4096
    const int blocks = batch / WARPS_PER_BLOCK;      // 1024

    lstm_kernel<<<blocks, THREADS_PER_BLOCK>>>(x, Wi, Wh, bh, Wo, bo, out);
}

// round 11
// speedup vs baseline: 2.8634x; 2.8634x over previous
#include <cuda_runtime.h>
#include <cuda_fp16.h>
#include <cstdint>

// Problem constants (fixed by the dataset)
#define LL 256
#define MTILE 16   // batch rows per warp

typedef unsigned int u32;
typedef unsigned long long ull;

// ---------- f32x2 packed helpers ----------
__device__ __forceinline__ ull pack2(float a, float b) {
    ull r;
    asm("mov.b64 %0, {%1, %2};" : "=l"(r)
        : "r"(__float_as_uint(a)), "r"(__float_as_uint(b)));
    return r;
}
__device__ __forceinline__ void unpack2(ull v, float& a, float& b) {
    u32 x, y;
    asm("mov.b64 {%0, %1}, %2;" : "=r"(x), "=r"(y) : "l"(v));
    a = __uint_as_float(x);
    b = __uint_as_float(y);
}
__device__ __forceinline__ ull fma2(ull a, ull b, ull c) {
    ull d;
    asm("fma.rn.f32x2 %0, %1, %2, %3;" : "=l"(d) : "l"(a), "l"(b), "l"(c));
    return d;
}
__device__ __forceinline__ ull add2(ull a, ull b) {
    ull d;
    asm("add.rn.f32x2 %0, %1, %2;" : "=l"(d) : "l"(a), "l"(b));
    return d;
}

// HW tanh (MUFU.TANH): ~1e-4 abs error
__device__ __forceinline__ float tanh_fast(float x) {
    float y;
    asm("tanh.approx.f32 %0, %1;" : "=f"(y) : "f"(x));
    return y;
}

// cvt.rn.f16x2.f32 d, a, b -> d = {hi = a, lo = b}
__device__ __forceinline__ u32 f16x2_of(float hi, float lo) {
    u32 r;
    asm("cvt.rn.f16x2.f32 %0, %1, %2;" : "=r"(r) : "f"(hi), "f"(lo));
    return r;
}

// mma.sync m16n8k16 row.col f32.f16.f16.f32
__device__ __forceinline__ void mma16816(
    float& d0, float& d1, float& d2, float& d3,
    u32 a0, u32 a1, u32 a2, u32 a3,
    u32 b0, u32 b1,
    float c0, float c1, float c2, float c3)
{
    asm("mma.sync.aligned.m16n8k16.row.col.f32.f16.f16.f32 "
        "{%0,%1,%2,%3}, {%4,%5,%6,%7}, {%8,%9}, {%10,%11,%12,%13};"
        : "=f"(d0), "=f"(d1), "=f"(d2), "=f"(d3)
        : "r"(a0), "r"(a1), "r"(a2), "r"(a3),
          "r"(b0), "r"(b1),
          "f"(c0), "f"(c1), "f"(c2), "f"(c3));
}

// Extended weight matrix element: rows 0..31 = Wh, 32/33 = Wi[0]/Wi[1],
// 34 = bh, 35..47 = 0. Columns: 0-31 i, 32-63 f, 64-95 g, 96-127 o.
// 0.5 prescale on i,f,o (sigmoid(x) = 0.5*tanh(0.5x)+0.5).
__device__ __forceinline__ float wval(int k, int col,
                                      const float* __restrict__ Wh,
                                      const float* __restrict__ Wi,
                                      const float* __restrict__ bh) {
    float v = 0.f;
    if (k < 32) v = Wh[k * 128 + col];
    else if (k == 32) v = Wi[col];
    else if (k == 33) v = Wi[128 + col];
    else if (k == 34) v = bh[col];
    float s = (col >= 64 && col < 96) ? 1.f : 0.5f;
    return v * s;
}

// One warp owns 16 batch rows. Per step, gates[16,128] = A_ext[16,48] @
// B_ext[48,128] via 48 HMMA (16 n-tiles x 3 k-tiles), where A_ext =
// [h (fp16) | onehot(prev spin), 1(bh), 0...]. The m16n8 D layout
// (lane(g,t): rows g,g+8, cols 8m+2t..+1 in tile m) IS the m16k16 A layout
// needed next step (k-slot 2t of k-tile kt <- group 2*kt... ), so the
// recurrence is entirely lane-local: activations -> cvt fp16x2 -> next A.
// No smem, no shuffles in the recurrence. Head: per-lane partial dot, one
// quad shfl reduce, softmax, predicated logp accumulate.
__global__ void __launch_bounds__(32)
lstm_kernel(const int* __restrict__ x,       // [B, L] spins in {0,1}
            const float* __restrict__ Wi,    // [2, 128]
            const float* __restrict__ Wh,    // [32, 128]
            const float* __restrict__ bh,    // [128]
            const float* __restrict__ Wo,    // [32, 2]
            const float* __restrict__ bo,    // [2]
            float* __restrict__ out)         // [B]
{
    __shared__ unsigned char s_x[MTILE * LL];

    const int lane = threadIdx.x & 31;
    const int g = lane >> 2;      // groupID: rows g, g+8
    const int t = lane & 3;       // threadID in group
    const int base_b = blockIdx.x * MTILE;

    // stage this tile's spins (coalesced LDG)
    for (int idx = lane; idx < MTILE * LL; idx += 32)
        s_x[idx] = (unsigned char)x[base_b * LL + idx];   // [row][t]
    __syncwarp();

    // ---- B fragments (fp16, register-resident, one-time build) ----
    // b0 = {lo=B[k0][col], hi=B[k0+1][col]}, b1 = k0+8 pair; col = 8*nt+g
    u32 bf[16][3][2];
#pragma unroll
    for (int nt = 0; nt < 16; nt++) {
        const int col = nt * 8 + g;
#pragma unroll
        for (int kt = 0; kt < 3; kt++) {
            const int k0 = kt * 16 + 2 * t;
            bf[nt][kt][0] = f16x2_of(wval(k0 + 1, col, Wh, Wi, bh),
                                     wval(k0,     col, Wh, Wi, bh));
            bf[nt][kt][1] = f16x2_of(wval(k0 + 9, col, Wh, Wi, bh),
                                     wval(k0 + 8, col, Wh, Wi, bh));
        }
    }

    // output-head weights for my 8 units (u = 8m+2t, 8m+2t+1)
    ull wo[8];
#pragma unroll
    for (int m = 0; m < 4; m++) {
        const int u = 8 * m + 2 * t;
        wo[2 * m]     = pack2(Wo[2 * u],     Wo[2 * u + 1]);
        wo[2 * m + 1] = pack2(Wo[2 * u + 2], Wo[2 * u + 3]);
    }
    const float bo0 = bo[0];
    const float bo1 = bo[1];

    // state
    float cst[16];                 // c for my 16 (row,unit) slots
#pragma unroll
    for (int i = 0; i < 16; i++) cst[i] = 0.f;
    u32 A0[4] = {0, 0, 0, 0};      // A k-tile 0 (h, k=0..15) — h=0 at t=0
    u32 A1[4] = {0, 0, 0, 0};      // A k-tile 1 (h, k=16..31)
    int sel_g = 2, sel_g8 = 2;     // 2 = zero input row (t=0)
    float logp = 0.f;
    const u32 eaC = f16x2_of(0.f, 1.f);   // t==1 ext-A const: k34=1 (bh), k35=0
    const float zf = 0.f;

#pragma unroll 1
    for (int step = 0; step < LL; step++) {
        // ---- ext A fragment (k=32..47): onehot(sel) at k32/33, 1 at k34 ----
        float lo0 = (t == 0) ? ((sel_g  == 0) ? 1.f : 0.f) : 0.f;
        float hi0 = (t == 0) ? ((sel_g  == 1) ? 1.f : 0.f) : 0.f;
        float lo1 = (t == 0) ? ((sel_g8 == 0) ? 1.f : 0.f) : 0.f;
        float hi1 = (t == 0) ? ((sel_g8 == 1) ? 1.f : 0.f) : 0.f;
        u32 ea0 = f16x2_of(hi0, lo0);
        u32 ea1 = f16x2_of(hi1, lo1);
        ea0 = (t == 1) ? eaC : ea0;
        ea1 = (t == 1) ? eaC : ea1;

        u32 nA0[4], nA1[4];
        ull accg = 0ull, accg8 = 0ull;

#pragma unroll
        for (int m = 0; m < 4; m++) {
            float ci0, ci1, ci2, ci3;   // i-gate tile m
            float cf0, cf1, cf2, cf3;   // f-gate tile m+4
            float cg0, cg1, cg2, cg3;   // g-gate tile m+8
            float co0, co1, co2, co3;   // o-gate tile m+12

            mma16816(ci0,ci1,ci2,ci3, A0[0],A0[1],A0[2],A0[3], bf[m][0][0],bf[m][0][1], zf,zf,zf,zf);
            mma16816(ci0,ci1,ci2,ci3, A1[0],A1[1],A1[2],A1[3], bf[m][1][0],bf[m][1][1], ci0,ci1,ci2,ci3);
            mma16816(ci0,ci1,ci2,ci3, ea0,ea1,0u,0u,           bf[m][2][0],bf[m][2][1], ci0,ci1,ci2,ci3);

            mma16816(cf0,cf1,cf2,cf3, A0[0],A0[1],A0[2],A0[3], bf[m+4][0][0],bf[m+4][0][1], zf,zf,zf,zf);
            mma16816(cf0,cf1,cf2,cf3, A1[0],A1[1],A1[2],A1[3], bf[m+4][1][0],bf[m+4][1][1], cf0,cf1,cf2,cf3);
            mma16816(cf0,cf1,cf2,cf3, ea0,ea1,0u,0u,           bf[m+4][2][0],bf[m+4][2][1], cf0,cf1,cf2,cf3);

            mma16816(cg0,cg1,cg2,cg3, A0[0],A0[1],A0[2],A0[3], bf[m+8][0][0],bf[m+8][0][1], zf,zf,zf,zf);
            mma16816(cg0,cg1,cg2,cg3, A1[0],A1[1],A1[2],A1[3], bf[m+8][1][0],bf[m+8][1][1], cg0,cg1,cg2,cg3);
            mma16816(cg0,cg1,cg2,cg3, ea0,ea1,0u,0u,           bf[m+8][2][0],bf[m+8][2][1], cg0,cg1,cg2,cg3);

            mma16816(co0,co1,co2,co3, A0[0],A0[1],A0[2],A0[3], bf[m+12][0][0],bf[m+12][0][1], zf,zf,zf,zf);
            mma16816(co0,co1,co2,co3, A1[0],A1[1],A1[2],A1[3], bf[m+12][1][0],bf[m+12][1][1], co0,co1,co2,co3);
            mma16816(co0,co1,co2,co3, ea0,ea1,0u,0u,           bf[m+12][2][0],bf[m+12][2][1], co0,co1,co2,co3);

            // ---- activations: 4 slots (row g/g+8 x unit u0/u0+1) ----
            float h0, h1, h2, h3;
            {
                float si = fmaf(0.5f, tanh_fast(ci0), 0.5f);
                float sf = fmaf(0.5f, tanh_fast(cf0), 0.5f);
                float so = fmaf(0.5f, tanh_fast(co0), 0.5f);
                float tg = tanh_fast(cg0);
                float cn = fmaf(sf, cst[4 * m + 0], si * tg);
                cst[4 * m + 0] = cn;
                h0 = so * tanh_fast(cn);
            }
            {
                float si = fmaf(0.5f, tanh_fast(ci1), 0.5f);
                float sf = fmaf(0.5f, tanh_fast(cf1), 0.5f);
                float so = fmaf(0.5f, tanh_fast(co1), 0.5f);
                float tg = tanh_fast(cg1);
                float cn = fmaf(sf, cst[4 * m + 1], si * tg);
                cst[4 * m + 1] = cn;
                h1 = so * tanh_fast(cn);
            }
            {
                float si = fmaf(0.5f, tanh_fast(ci2), 0.5f);
                float sf = fmaf(0.5f, tanh_fast(cf2), 0.5f);
                float so = fmaf(0.5f, tanh_fast(co2), 0.5f);
                float tg = tanh_fast(cg2);
                float cn = fmaf(sf, cst[4 * m + 2], si * tg);
                cst[4 * m + 2] = cn;
                h2 = so * tanh_fast(cn);
            }
            {
                float si = fmaf(0.5f, tanh_fast(ci3), 0.5f);
                float sf = fmaf(0.5f, tanh_fast(cf3), 0.5f);
                float so = fmaf(0.5f, tanh_fast(co3), 0.5f);
                float tg = tanh_fast(cg3);
                float cn = fmaf(sf, cst[4 * m + 3], si * tg);
                cst[4 * m + 3] = cn;
                h3 = so * tanh_fast(cn);
            }

            // D layout == next-step A layout: lane-local handoff
            const u32 pg  = f16x2_of(h1, h0);   // row g:   (lo=u0, hi=u0+1)
            const u32 pg8 = f16x2_of(h3, h2);   // row g+8
            if (m == 0)      { nA0[0] = pg; nA0[1] = pg8; }
            else if (m == 1) { nA0[2] = pg; nA0[3] = pg8; }
            else if (m == 2) { nA1[0] = pg; nA1[1] = pg8; }
            else             { nA1[2] = pg; nA1[3] = pg8; }

            // output-head partial dots
            accg  = fma2(pack2(h0, h0), wo[2 * m],     accg);
            accg  = fma2(pack2(h1, h1), wo[2 * m + 1], accg);
            accg8 = fma2(pack2(h2, h2), wo[2 * m],     accg8);
            accg8 = fma2(pack2(h3, h3), wo[2 * m + 1], accg8);
        }

        // ---- head: reduce over the quad (lanes sharing g) ----
        accg  = add2(accg,  __shfl_xor_sync(0xffffffffu, accg,  1));
        accg  = add2(accg,  __shfl_xor_sync(0xffffffffu, accg,  2));
        accg8 = add2(accg8, __shfl_xor_sync(0xffffffffu, accg8, 1));
        accg8 = add2(accg8, __shfl_xor_sync(0xffffffffu, accg8, 2));

        float p0g, p1g, p0h, p1h;
        unpack2(accg, p0g, p1g);
        unpack2(accg8, p0h, p1h);
        p0g += bo0; p1g += bo1;
        p0h += bo0; p1h += bo1;

        const int cur_g  = (int)s_x[g * LL + step];
        const int cur_g8 = (int)s_x[(g + 8) * LL + step];

        // elu + 2-class gathered log-softmax per row
        float e0 = (p0g > 0.f) ? p0g : (__expf(p0g) - 1.f);
        float e1 = (p1g > 0.f) ? p1g : (__expf(p1g) - 1.f);
        float dg = cur_g ? (e0 - e1) : (e1 - e0);
        float lpg = __logf(1.f + __expf(dg));

        float f0 = (p0h > 0.f) ? p0h : (__expf(p0h) - 1.f);
        float f1 = (p1h > 0.f) ? p1h : (__expf(p1h) - 1.f);
        float dh = cur_g8 ? (f0 - f1) : (f1 - f0);
        float lph = __logf(1.f + __expf(dh));

        logp -= (t == 0) ? lpg : (t == 1) ? lph : 0.f;

        sel_g = cur_g;
        sel_g8 = cur_g8;
#pragma unroll
        for (int i = 0; i < 4; i++) { A0[i] = nA0[i]; A1[i] = nA1[i]; }
    }

    if (t == 0)      out[base_b + g]     = 0.5f * logp;
    else if (t == 1) out[base_b + 8 + g] = 0.5f * logp;
}

extern "C" void kernel_launch(void* const* d_in, const int* in_sizes, int n_in,
                              void* d_out, int out_size) {
    const int* x = (const int*)d_in[0];
    const float* Wi = (const float*)d_in[1];
    const float* Wh = (const float*)d_in[2];
    const float* bh = (const float*)d_in[3];
    const float* Wo = (const float*)d_in[4];
    const float* bo = (const float*)d_in[5];
    float* out = (float*)d_out;

    const int batch = in_sizes[0] / LL;          // 4096
    const int blocks = batch / MTILE;            // 256 single-warp blocks

    lstm_kernel<<<blocks, 32>>>(x, Wi, Wh, bh, Wo, bo, out);
}

// round 12
// speedup vs baseline: 4.0913x; 1.4288x over previous
#include <cuda_runtime.h>
#include <cuda_fp16.h>
#include <cstdint>

// Problem constants (fixed by the dataset)
#define LL 256
#define ROWS_PER_WARP 8
#define WARPS_PER_BLOCK 4
#define THREADS_PER_BLOCK (WARPS_PER_BLOCK * 32)
#define ROWS_PER_BLOCK (WARPS_PER_BLOCK * ROWS_PER_WARP)   // 32

typedef unsigned int u32;
typedef unsigned long long ull;

// ---------- f32x2 packed helpers ----------
__device__ __forceinline__ ull pack2(float a, float b) {
    ull r;
    asm("mov.b64 %0, {%1, %2};" : "=l"(r)
        : "r"(__float_as_uint(a)), "r"(__float_as_uint(b)));
    return r;
}
__device__ __forceinline__ void unpack2(ull v, float& a, float& b) {
    u32 x, y;
    asm("mov.b64 {%0, %1}, %2;" : "=r"(x), "=r"(y) : "l"(v));
    a = __uint_as_float(x);
    b = __uint_as_float(y);
}
__device__ __forceinline__ ull fma2(ull a, ull b, ull c) {
    ull d;
    asm("fma.rn.f32x2 %0, %1, %2, %3;" : "=l"(d) : "l"(a), "l"(b), "l"(c));
    return d;
}
__device__ __forceinline__ ull add2(ull a, ull b) {
    ull d;
    asm("add.rn.f32x2 %0, %1, %2;" : "=l"(d) : "l"(a), "l"(b));
    return d;
}

// HW tanh (MUFU.TANH): ~1e-4 abs error
__device__ __forceinline__ float tanh_fast(float x) {
    float y;
    asm("tanh.approx.f32 %0, %1;" : "=f"(y) : "f"(x));
    return y;
}

// cvt.rn.f16x2.f32 d, a, b -> d = {hi = a, lo = b}
__device__ __forceinline__ u32 f16x2_of(float hi, float lo) {
    u32 r;
    asm("cvt.rn.f16x2.f32 %0, %1, %2;" : "=r"(r) : "f"(hi), "f"(lo));
    return r;
}

// mma.sync m16n8k16 row.col f32.f16.f16.f32
__device__ __forceinline__ void mma16816(
    float& d0, float& d1, float& d2, float& d3,
    u32 a0, u32 a1, u32 a2, u32 a3,
    u32 b0, u32 b1,
    float c0, float c1, float c2, float c3)
{
    asm("mma.sync.aligned.m16n8k16.row.col.f32.f16.f16.f32 "
        "{%0,%1,%2,%3}, {%4,%5,%6,%7}, {%8,%9}, {%10,%11,%12,%13};"
        : "=f"(d0), "=f"(d1), "=f"(d2), "=f"(d3)
        : "r"(a0), "r"(a1), "r"(a2), "r"(a3),
          "r"(b0), "r"(b1),
          "f"(c0), "f"(c1), "f"(c2), "f"(c3));
}

// Extended weight matrix: rows 0..31 = Wh, 32/33 = Wi[0]/Wi[1], 34 = bh,
// 35..47 = 0. Columns: 0-31 i, 32-63 f, 64-95 g, 96-127 o.
// 0.5 prescale on i,f,o (sigmoid(x) = 0.5*tanh(0.5x)+0.5).
__device__ __forceinline__ float wval(int k, int col,
                                      const float* __restrict__ Wh,
                                      const float* __restrict__ Wi,
                                      const float* __restrict__ bh) {
    float v = 0.f;
    if (k < 32) v = Wh[k * 128 + col];
    else if (k == 32) v = Wi[col];
    else if (k == 33) v = Wi[128 + col];
    else if (k == 34) v = bh[col];
    float s = (col >= 64 && col < 96) ? 1.f : 0.5f;
    return v * s;
}

// Each WARP owns 8 batch rows (rows 8-15 of the m16 tile are pinned to zero:
// their A slots stay 0, their D slots are never read -> no activations, no
// MUFU for them). 4 warps per block so warps land on SMSPs 0-3 (wid%4) with
// one block per SM: each warp gets a private scheduler + MUFU unit. Warps
// are fully independent after setup (no per-step block sync — R7 lesson).
// Recurrence is lane-local: D fragment layout == next-step A fragment layout.
__global__ void __launch_bounds__(THREADS_PER_BLOCK)
lstm_kernel(const int* __restrict__ x,       // [B, L] spins in {0,1}
            const float* __restrict__ Wi,    // [2, 128]
            const float* __restrict__ Wh,    // [32, 128]
            const float* __restrict__ bh,    // [128]
            const float* __restrict__ Wo,    // [32, 2]
            const float* __restrict__ bo,    // [2]
            float* __restrict__ out)         // [B]
{
    __shared__ unsigned char s_x[ROWS_PER_BLOCK * LL];

    const int tid = threadIdx.x;
    const int lane = tid & 31;
    const int warp = tid >> 5;
    const int g = lane >> 2;      // groupID: my valid row is g (row g+8 unused)
    const int t = lane & 3;       // threadID in group
    const int base_b = blockIdx.x * ROWS_PER_BLOCK + warp * ROWS_PER_WARP;

    // stage the block's spins (coalesced LDG)
    {
        const int blk_b = blockIdx.x * ROWS_PER_BLOCK;
        for (int idx = tid; idx < ROWS_PER_BLOCK * LL; idx += THREADS_PER_BLOCK)
            s_x[idx] = (unsigned char)x[blk_b * LL + idx];
    }
    __syncthreads();
    const unsigned char* xw = s_x + (warp * ROWS_PER_WARP) * LL;  // my 8 rows

    // ---- B fragments (fp16, register-resident, one-time build) ----
    u32 bf[16][3][2];
#pragma unroll
    for (int nt = 0; nt < 16; nt++) {
        const int col = nt * 8 + g;
#pragma unroll
        for (int kt = 0; kt < 3; kt++) {
            const int k0 = kt * 16 + 2 * t;
            bf[nt][kt][0] = f16x2_of(wval(k0 + 1, col, Wh, Wi, bh),
                                     wval(k0,     col, Wh, Wi, bh));
            bf[nt][kt][1] = f16x2_of(wval(k0 + 9, col, Wh, Wi, bh),
                                     wval(k0 + 8, col, Wh, Wi, bh));
        }
    }

    // output-head weights for my 8 units (u = 8m+2t, 8m+2t+1)
    ull wo[8];
#pragma unroll
    for (int m = 0; m < 4; m++) {
        const int u = 8 * m + 2 * t;
        wo[2 * m]     = pack2(Wo[2 * u],     Wo[2 * u + 1]);
        wo[2 * m + 1] = pack2(Wo[2 * u + 2], Wo[2 * u + 3]);
    }
    const float bo0 = bo[0];
    const float bo1 = bo[1];

    // state: row g only (2 slots per m-tile)
    float cst[8];
#pragma unroll
    for (int i = 0; i < 8; i++) cst[i] = 0.f;
    // A fragments: slots {a0,a2} = row g, {a1,a3} = row g+8 (always 0)
    u32 A0[4] = {0, 0, 0, 0};
    u32 A1[4] = {0, 0, 0, 0};
    int sel_g = 2;                 // 2 = zero input row (t=0)
    float logp = 0.f;
    const u32 eaC = f16x2_of(0.f, 1.f);   // t==1 ext-A: k34=1 (bh), k35=0
    const float zf = 0.f;

#pragma unroll 1
    for (int step = 0; step < LL; step++) {
        // ---- ext A fragment (k=32..47): onehot(sel) k32/33, 1 at k34 ----
        float lo0 = (t == 0) ? ((sel_g == 0) ? 1.f : 0.f) : 0.f;
        float hi0 = (t == 0) ? ((sel_g == 1) ? 1.f : 0.f) : 0.f;
        u32 ea0 = f16x2_of(hi0, lo0);
        ea0 = (t == 1) ? eaC : ea0;

        u32 nA0[4], nA1[4];
        nA0[1] = 0u; nA0[3] = 0u; nA1[1] = 0u; nA1[3] = 0u;  // rows 8-15 = 0
        ull accg = 0ull;

#pragma unroll
        for (int m = 0; m < 4; m++) {
            float ci0, ci1, ci2, ci3;
            float cf0, cf1, cf2, cf3;
            float cg0, cg1, cg2, cg3;
            float co0, co1, co2, co3;

            mma16816(ci0,ci1,ci2,ci3, A0[0],A0[1],A0[2],A0[3], bf[m][0][0],bf[m][0][1], zf,zf,zf,zf);
            mma16816(ci0,ci1,ci2,ci3, A1[0],A1[1],A1[2],A1[3], bf[m][1][0],bf[m][1][1], ci0,ci1,ci2,ci3);
            mma16816(ci0,ci1,ci2,ci3, ea0,0u,0u,0u,            bf[m][2][0],bf[m][2][1], ci0,ci1,ci2,ci3);

            mma16816(cf0,cf1,cf2,cf3, A0[0],A0[1],A0[2],A0[3], bf[m+4][0][0],bf[m+4][0][1], zf,zf,zf,zf);
            mma16816(cf0,cf1,cf2,cf3, A1[0],A1[1],A1[2],A1[3], bf[m+4][1][0],bf[m+4][1][1], cf0,cf1,cf2,cf3);
            mma16816(cf0,cf1,cf2,cf3, ea0,0u,0u,0u,            bf[m+4][2][0],bf[m+4][2][1], cf0,cf1,cf2,cf3);

            mma16816(cg0,cg1,cg2,cg3, A0[0],A0[1],A0[2],A0[3], bf[m+8][0][0],bf[m+8][0][1], zf,zf,zf,zf);
            mma16816(cg0,cg1,cg2,cg3, A1[0],A1[1],A1[2],A1[3], bf[m+8][1][0],bf[m+8][1][1], cg0,cg1,cg2,cg3);
            mma16816(cg0,cg1,cg2,cg3, ea0,0u,0u,0u,            bf[m+8][2][0],bf[m+8][2][1], cg0,cg1,cg2,cg3);

            mma16816(co0,co1,co2,co3, A0[0],A0[1],A0[2],A0[3], bf[m+12][0][0],bf[m+12][0][1], zf,zf,zf,zf);
            mma16816(co0,co1,co2,co3, A1[0],A1[1],A1[2],A1[3], bf[m+12][1][0],bf[m+12][1][1], co0,co1,co2,co3);
            mma16816(co0,co1,co2,co3, ea0,0u,0u,0u,            bf[m+12][2][0],bf[m+12][2][1], co0,co1,co2,co3);

            // ---- activations: row g only (slots 0 and 1) ----
            float h0, h1;
            {
                float si = fmaf(0.5f, tanh_fast(ci0), 0.5f);
                float sf = fmaf(0.5f, tanh_fast(cf0), 0.5f);
                float so = fmaf(0.5f, tanh_fast(co0), 0.5f);
                float tg = tanh_fast(cg0);
                float cn = fmaf(sf, cst[2 * m + 0], si * tg);
                cst[2 * m + 0] = cn;
                h0 = so * tanh_fast(cn);
            }
            {
                float si = fmaf(0.5f, tanh_fast(ci1), 0.5f);
                float sf = fmaf(0.5f, tanh_fast(cf1), 0.5f);
                float so = fmaf(0.5f, tanh_fast(co1), 0.5f);
                float tg = tanh_fast(cg1);
                float cn = fmaf(sf, cst[2 * m + 1], si * tg);
                cst[2 * m + 1] = cn;
                h1 = so * tanh_fast(cn);
            }
            (void)ci2; (void)ci3; (void)cf2; (void)cf3;
            (void)cg2; (void)cg3; (void)co2; (void)co3;

            // D layout == next-step A layout (lane-local handoff), row g only
            const u32 pg = f16x2_of(h1, h0);
            if (m == 0)      nA0[0] = pg;
            else if (m == 1) nA0[2] = pg;
            else if (m == 2) nA1[0] = pg;
            else             nA1[2] = pg;

            // output-head partial dots (row g)
            accg = fma2(pack2(h0, h0), wo[2 * m],     accg);
            accg = fma2(pack2(h1, h1), wo[2 * m + 1], accg);
        }

        // ---- head: reduce over the quad (lanes sharing g) ----
        accg = add2(accg, __shfl_xor_sync(0xffffffffu, accg, 1));
        accg = add2(accg, __shfl_xor_sync(0xffffffffu, accg, 2));

        float p0, p1;
        unpack2(accg, p0, p1);
        p0 += bo0;
        p1 += bo1;

        const int cur = (int)xw[g * LL + step];

        // elu + 2-class gathered log-softmax
        float e0 = (p0 > 0.f) ? p0 : (__expf(p0) - 1.f);
        float e1 = (p1 > 0.f) ? p1 : (__expf(p1) - 1.f);
        float dg = cur ? (e0 - e1) : (e1 - e0);
        float lpg = __logf(1.f + __expf(dg));
        logp -= (t == 0) ? lpg : 0.f;

        sel_g = cur;
#pragma unroll
        for (int i = 0; i < 4; i++) { A0[i] = nA0[i]; A1[i] = nA1[i]; }
    }

    if (t == 0)
        out[base_b + g] = 0.5f * logp;
}

extern "C" void kernel_launch(void* const* d_in, const int* in_sizes, int n_in,
                              void* d_out, int out_size) {
    const int* x = (const int*)d_in[0];
    const float* Wi = (const float*)d_in[1];
    const float* Wh = (const float*)d_in[2];
    const float* bh = (const float*)d_in[3];
    const float* Wo = (const float*)d_in[4];
    const float* bo = (const float*)d_in[5];
    float* out = (float*)d_out;

    const int batch = in_sizes[0] / LL;              // 4096
    const int blocks = batch / ROWS_PER_BLOCK;       // 128 blocks x 4 warps

    lstm_kernel<<<blocks, THREADS_PER_BLOCK>>>(x, Wi, Wh, bh, Wo, bo, out);
}